// round 14
// baseline (speedup 1.0000x reference)
#include <cstdint>
#include <cuda_runtime.h>
#include <cuda_fp16.h>
#include <math.h>
#include <float.h>

// Problem constants
#define Bc    2
#define Hh    64
#define Ww    160
#define DIMc  256
#define NHc   8
#define HDc   32
#define Nn    (Hh * Ww)       // 10240 tokens per batch
#define Mrows (Bc * Nn)       // 20480 total rows
#define SCALEF 0.17677669529663687f   // 32^-0.5

// Static scratch (all activations fp16, packed half2)
__device__ uint32_t g_qh[Mrows * 128];    // q, pre-scaled by SCALEF
__device__ uint32_t g_kh[Mrows * 128];
__device__ uint32_t g_vh[Mrows * 128];
__device__ uint32_t g_xh[Mrows * 128];    // X as fp16
__device__ uint32_t g_hf[Mrows * 128];    // attn output as fp16
__device__ uint32_t g_wf[2 * 4 * 32768];  // W fp16 planes: [hi|lo][w][k][n/2]
#define WLOFF_B 524288                    // byte offset of lo planes

// ---------------------------------------------------------------------------
// helpers
// ---------------------------------------------------------------------------
__device__ __forceinline__ uint32_t smem_to_u32(const void* smem_ptr) {
    uint32_t addr;
    asm("{ .reg .u64 tmp; cvta.to.shared.u64 tmp, %1; cvt.u32.u64 %0, tmp; }"
        : "=r"(addr) : "l"(smem_ptr));
    return addr;
}

__device__ __forceinline__ uint32_t f2h2(float x, float y) {   // lo=x, hi=y
    uint32_t u;
    asm("cvt.rn.f16x2.f32 %0, %1, %2;" : "=r"(u) : "f"(y), "f"(x));
    return u;
}

__device__ __forceinline__ void mma_f16(float* c, const uint32_t* a,
                                        uint32_t b0, uint32_t b1) {
    asm volatile(
        "mma.sync.aligned.m16n8k16.row.col.f32.f16.f16.f32 "
        "{%0,%1,%2,%3},{%4,%5,%6,%7},{%8,%9},{%0,%1,%2,%3};"
        : "+f"(c[0]), "+f"(c[1]), "+f"(c[2]), "+f"(c[3])
        : "r"(a[0]), "r"(a[1]), "r"(a[2]), "r"(a[3]), "r"(b0), "r"(b1));
}

__device__ __forceinline__ void ldsm_x4(uint32_t* r, uint32_t addr) {
    asm volatile(
        "ldmatrix.sync.aligned.m8n8.x4.shared.b16 {%0,%1,%2,%3}, [%4];"
        : "=r"(r[0]), "=r"(r[1]), "=r"(r[2]), "=r"(r[3]) : "r"(addr));
}

__device__ __forceinline__ void ldsm_x4_t(uint32_t* r, uint32_t addr) {
    asm volatile(
        "ldmatrix.sync.aligned.m8n8.x4.trans.shared.b16 {%0,%1,%2,%3}, [%4];"
        : "=r"(r[0]), "=r"(r[1]), "=r"(r[2]), "=r"(r[3]) : "r"(addr));
}

#define CP16(dst, src) \
    asm volatile("cp.async.cg.shared.global [%0], [%1], 16;" :: "r"(dst), "l"(src))
#define CP_COMMIT() asm volatile("cp.async.commit_group;")
#define CP_WAIT(n)  asm volatile("cp.async.wait_group %0;" :: "n"(n))

// ---------------------------------------------------------------------------
// Conversion: X -> fp16, W -> fp16 hi/lo planes
// ---------------------------------------------------------------------------
#define XBLKS ((Mrows * 128) / 256)   // 10240

__global__ void __launch_bounds__(256)
conv_all(const float* __restrict__ x,
         const float* __restrict__ Wq, const float* __restrict__ Wk,
         const float* __restrict__ Wv, const float* __restrict__ Wp) {
    const int b = blockIdx.x;
    if (b < XBLKS) {
        size_t id = (size_t)b * 256 + threadIdx.x;
        float2 v = *reinterpret_cast<const float2*>(x + id * 2);
        g_xh[id] = f2h2(v.x, v.y);
    } else {
        int id2 = (b - XBLKS) * 256 + threadIdx.x;   // 0 .. 131071
        int w = id2 >> 15;
        int id = id2 & 32767;
        const float* src = (w == 0) ? Wq : (w == 1) ? Wk : (w == 2) ? Wv : Wp;
        float2 v = *reinterpret_cast<const float2*>(src + (size_t)id * 2);
        uint32_t h = f2h2(v.x, v.y);
        __half2 hh = *reinterpret_cast<__half2*>(&h);
        float2 hf = __half22float2(hh);
        g_wf[w * 32768 + id] = h;
        g_wf[131072 + w * 32768 + id] = f2h2(v.x - hf.x, v.y - hf.y);
    }
}

// ---------------------------------------------------------------------------
// fp16x2 GEMM: C = A_fp16 @ (Whi + Wlo).  BM=64, BN=128, 256 threads
// (8 warps, 32x32 warp tiles).  3-buffer ring of k32 chunks, cp.async,
// sized for 3 CTAs/SM (smem 67584, regs capped via launch_bounds).
// A smem: [m][k] fp16, row stride 80 B.  B smem: hi/lo [k][n], stride 272 B.
// ---------------------------------------------------------------------------
#define A_ST   5120              // 64 rows * 80 B
#define BH_ST  8704              // 32 rows * 272 B
#define SUB    22528             // A_ST + 2*BH_ST
#define SMEM_GEMM (3 * SUB)      // 67584
#define AROW_B 512               // gmem fp16 activation row bytes

__device__ __forceinline__ void issue_chunk(
    uint32_t buf, int g, const char* Ag, const char* Wh,
    uint32_t ad0, uint32_t bd0)
{
    CP16(buf + ad0, Ag + g * 64);
    const char* wh = Wh + g * 16384;         // 32 k-rows * 512 B
    CP16(buf + bd0, wh);
    CP16(buf + bd0 + 16 * 272, wh + 16 * 512);
    const char* wl = Wh + WLOFF_B + g * 16384;
    CP16(buf + bd0 + BH_ST, wl);
    CP16(buf + bd0 + BH_ST + 16 * 272, wl + 16 * 512);
    CP_COMMIT();
}

__device__ __forceinline__ void gemm_body(const uint32_t* __restrict__ Asrc,
                                          const uint32_t* __restrict__ Wplane,
                                          float* __restrict__ Cf,
                                          uint32_t* __restrict__ Ch,
                                          float qscale) {
    extern __shared__ char smem_c[];
    const uint32_t sb = smem_to_u32(smem_c);
    const int t    = threadIdx.x;
    const int warp = t >> 5;
    const int lane = t & 31;
    const int q    = lane >> 2;
    const int c4   = lane & 3;
    const int bm = blockIdx.y * 64;
    const int bn = blockIdx.x * 128;
    const int wm = (warp >> 2) * 32;
    const int wn = (warp & 3) * 32;

    const char* Ag = (const char*)Asrc + (size_t)(bm + (t >> 2)) * AROW_B + (t & 3) * 16;
    const char* Wh = (const char*)Wplane + (size_t)(t >> 4) * 512 + bn * 2 + (t & 15) * 16;
    const uint32_t ad0 = (uint32_t)((t >> 2) * 80 + (t & 3) * 16);
    const uint32_t bd0 = (uint32_t)(A_ST + (t >> 4) * 272 + (t & 15) * 16);

    float acc[2][4][4];
#pragma unroll
    for (int i = 0; i < 2; i++)
#pragma unroll
        for (int j = 0; j < 4; j++)
#pragma unroll
            for (int e = 0; e < 4; e++) acc[i][j][e] = 0.f;

    issue_chunk(sb,       0, Ag, Wh, ad0, bd0);
    issue_chunk(sb + SUB, 1, Ag, Wh, ad0, bd0);

    int cbuf = 0;   // buffer of chunk g
    int nbuf = 2;   // next buffer to fill
#pragma unroll 1
    for (int g = 0; g < 8; g++) {
        if (g < 7) { CP_WAIT(1); } else { CP_WAIT(0); }
        __syncthreads();
        if (g < 6) {
            issue_chunk(sb + nbuf * SUB, g + 2, Ag, Wh, ad0, bd0);
            nbuf = (nbuf == 2) ? 0 : nbuf + 1;
        }

        const uint32_t abase = sb + cbuf * SUB;
        const uint32_t bhb = abase + A_ST;
        const uint32_t blb = bhb + BH_ST;
        cbuf = (cbuf == 2) ? 0 : cbuf + 1;

#pragma unroll
        for (int k16 = 0; k16 < 2; k16++) {
            uint32_t a[2][4];
#pragma unroll
            for (int mt = 0; mt < 2; mt++) {
                ldsm_x4(a[mt], abase + (wm + mt * 16 + (lane & 15)) * 80
                             + k16 * 32 + (lane >> 4) * 16);
            }
            uint32_t bh[2][4], bl[2][4];
#pragma unroll
            for (int nc = 0; nc < 2; nc++) {
                uint32_t off = (uint32_t)((k16 * 16 + (lane & 15)) * 272
                              + (wn + nc * 16 + ((lane >> 4) << 3)) * 2);
                ldsm_x4_t(bh[nc], bhb + off);
                ldsm_x4_t(bl[nc], blb + off);
            }
#pragma unroll
            for (int mt = 0; mt < 2; mt++)
#pragma unroll
                for (int n8 = 0; n8 < 4; n8++) {
                    const int nc = n8 >> 1, jj = (n8 & 1) * 2;
                    mma_f16(acc[mt][n8], a[mt], bh[nc][jj], bh[nc][jj + 1]);
                    mma_f16(acc[mt][n8], a[mt], bl[nc][jj], bl[nc][jj + 1]);
                }
        }
    }

    // epilogue
    if (Ch) {
#pragma unroll
        for (int mt = 0; mt < 2; mt++)
#pragma unroll
            for (int n8 = 0; n8 < 4; n8++) {
                const int gr0 = bm + wm + mt * 16 + q;
                const int gc  = bn + wn + n8 * 8 + 2 * c4;
                Ch[(size_t)gr0 * 128 + (gc >> 1)] =
                    f2h2(acc[mt][n8][0] * qscale, acc[mt][n8][1] * qscale);
                Ch[(size_t)(gr0 + 8) * 128 + (gc >> 1)] =
                    f2h2(acc[mt][n8][2] * qscale, acc[mt][n8][3] * qscale);
            }
    } else {
#pragma unroll
        for (int mt = 0; mt < 2; mt++)
#pragma unroll
            for (int n8 = 0; n8 < 4; n8++) {
                const int gr0 = bm + wm + mt * 16 + q;
                const int gc  = bn + wn + n8 * 8 + 2 * c4;
                *reinterpret_cast<float2*>(Cf + (size_t)gr0 * DIMc + gc) =
                    make_float2(acc[mt][n8][0], acc[mt][n8][1]);
                *reinterpret_cast<float2*>(Cf + (size_t)(gr0 + 8) * DIMc + gc) =
                    make_float2(acc[mt][n8][2], acc[mt][n8][3]);
            }
    }
}

__global__ void __launch_bounds__(256, 3)
gemm_qkv() {
    const int z = blockIdx.z;
    uint32_t* Ch = (z == 0) ? g_qh : (z == 1) ? g_kh : g_vh;
    gemm_body(g_xh, g_wf + z * 32768, nullptr, Ch, (z == 0) ? SCALEF : 1.f);
}

__global__ void __launch_bounds__(256, 3)
gemm_proj(float* __restrict__ out) {
    gemm_body(g_hf, g_wf + 3 * 32768, out, nullptr, 1.f);
}

// ---------------------------------------------------------------------------
// Attention: block-cooperative smem gather of the 16 window rows (k+v),
// then per-warp (head) scoring from smem.  Warp lanes: g=dim group (4 dims),
// sd=window column.  Position a = 4*dy + dx -> smem row dy*4+dx.
// smem row stride 144 words: LDS.64 reads conflict-free (sd*144%32 = {0,16}).
// ---------------------------------------------------------------------------
#define SROW 144

__global__ void __launch_bounds__(256, 6)
attn_kernel(const float* __restrict__ mo) {
    __shared__ uint32_t ks[16 * SROW];
    __shared__ uint32_t vs[16 * SROW];

    const int r = blockIdx.x;
    const int bofs = (r >= Nn) ? Nn : 0;
    const int t = threadIdx.x;
    const int hd = t >> 5;
    const int lane = t & 31;
    const int g  = lane & 7;
    const int sd = lane >> 3;

    float2 o2 = *reinterpret_cast<const float2*>(mo + (size_t)r * 2);
    float ox = fminf(fmaxf(o2.x, 1.0f), (float)(Ww - 2) - 0.001f);
    float oy = fminf(fmaxf(o2.y, 1.0f), (float)(Hh - 2) - 0.001f);
    const float mx = floorf(ox), my = floorf(oy);
    const float fx = ox - mx,   fy = oy - my;
    const int ibase = bofs + ((int)my - 1) * Ww + ((int)mx - 1);

    // cooperative gather: 16 rows x 512 B each of k and v, coalesced uint4
#pragma unroll
    for (int i = 0; i < 2; i++) {
        int id = t + i * 256;            // 0..511
        int row = id >> 5;               // 0..15  (dy = row>>2, dx = row&3)
        int c16 = id & 31;               // uint4 within row
        size_t gro = (size_t)(ibase + (row >> 2) * Ww + (row & 3)) * 128 + c16 * 4;
        *reinterpret_cast<uint4*>(&ks[row * SROW + c16 * 4]) =
            *reinterpret_cast<const uint4*>(g_kh + gro);
        *reinterpret_cast<uint4*>(&vs[row * SROW + c16 * 4]) =
            *reinterpret_cast<const uint4*>(g_vh + gro);
    }

    // q: 4 dims fp16 (pre-scaled)
    uint2 qq = *reinterpret_cast<const uint2*>(
        g_qh + (size_t)r * 128 + hd * 16 + g * 2);
    const float2 q01 = __half22float2(*reinterpret_cast<const __half2*>(&qq.x));
    const float2 q23 = __half22float2(*reinterpret_cast<const __half2*>(&qq.y));

    __syncthreads();

    const int woff = hd * 16 + g * 2;
    float part[4];
#pragma unroll
    for (int i = 0; i < 4; i++) {
        uint2 kk = *reinterpret_cast<const uint2*>(&ks[(i * 4 + sd) * SROW + woff]);
        float2 k01 = __half22float2(*reinterpret_cast<const __half2*>(&kk.x));
        float2 k23 = __half22float2(*reinterpret_cast<const __half2*>(&kk.y));
        part[i] = q01.x * k01.x + q01.y * k01.y + q23.x * k23.x + q23.y * k23.y;
    }

    // 4-value butterfly within 8-lane groups (offsets 4,2,1)
    float u2[2];
    {
        const bool hb = (lane & 4) != 0;
#pragma unroll
        for (int j = 0; j < 2; j++) {
            float keep = hb ? part[j + 2] : part[j];
            float send = hb ? part[j] : part[j + 2];
            u2[j] = keep + __shfl_xor_sync(0xffffffffu, send, 4);
        }
    }
    float u1;
    {
        const bool hb = (lane & 2) != 0;
        float keep = hb ? u2[1] : u2[0];
        float send = hb ? u2[0] : u2[1];
        u1 = keep + __shfl_xor_sync(0xffffffffu, send, 2);
    }
    const float s = u1 + __shfl_xor_sync(0xffffffffu, u1, 1);
    // lane holds score of position a = 4*i_mine + sd, i_mine = (lane>>1)&3

    const int i_mine = (lane >> 1) & 3;
    const float wxv = (sd == 0) ? (1.f - fx) : ((sd == 3) ? fx : 1.f);
    const float wyv = (i_mine == 0) ? (1.f - fy) : ((i_mine == 3) ? fy : 1.f);
    const float bw = wxv * wyv;

    float mval = s;
#pragma unroll
    for (int o = 16; o > 0; o >>= 1)
        mval = fmaxf(mval, __shfl_xor_sync(0xffffffffu, mval, o));
    const float e = __expf(s - mval) * bw;
    float se = e;
#pragma unroll
    for (int o = 16; o > 0; o >>= 1)
        se += __shfl_xor_sync(0xffffffffu, se, o);
    const float p = __fdividef(e, 0.5f * se);

    // V accumulate (4 dims): p for a=4i+sd lives in lane (sd<<3)|(i<<1)
    float f0 = 0.f, f1 = 0.f, f2 = 0.f, f3 = 0.f;
#pragma unroll
    for (int i = 0; i < 4; i++) {
        uint2 vv = *reinterpret_cast<const uint2*>(&vs[(i * 4 + sd) * SROW + woff]);
        float2 v01 = __half22float2(*reinterpret_cast<const __half2*>(&vv.x));
        float2 v23 = __half22float2(*reinterpret_cast<const __half2*>(&vv.y));
        float pa = __shfl_sync(0xffffffffu, p, (lane & 24) | (i << 1));
        f0 += pa * v01.x;
        f1 += pa * v01.y;
        f2 += pa * v23.x;
        f3 += pa * v23.y;
    }
#pragma unroll
    for (int o = 8; o <= 16; o <<= 1) {
        f0 += __shfl_xor_sync(0xffffffffu, f0, o);
        f1 += __shfl_xor_sync(0xffffffffu, f1, o);
        f2 += __shfl_xor_sync(0xffffffffu, f2, o);
        f3 += __shfl_xor_sync(0xffffffffu, f3, o);
    }

    if (sd == 0) {
        uint2 o;
        o.x = f2h2(f0, f1);
        o.y = f2h2(f2, f3);
        *reinterpret_cast<uint2*>(g_hf + (size_t)r * 128 + hd * 16 + g * 2) = o;
    }
}

// ---------------------------------------------------------------------------
extern "C" void kernel_launch(void* const* d_in, const int* in_sizes, int n_in,
                              void* d_out, int out_size) {
    const float* x  = (const float*)d_in[0];
    const float* mo = (const float*)d_in[1];
    const float* Wq = (const float*)d_in[2];
    const float* Wk = (const float*)d_in[3];
    const float* Wv = (const float*)d_in[4];
    const float* Wp = (const float*)d_in[5];
    float* out = (float*)d_out;

    cudaFuncSetAttribute(gemm_qkv, cudaFuncAttributeMaxDynamicSharedMemorySize, SMEM_GEMM);
    cudaFuncSetAttribute(gemm_proj, cudaFuncAttributeMaxDynamicSharedMemorySize, SMEM_GEMM);

    conv_all<<<XBLKS + 512, 256>>>(x, Wq, Wk, Wv, Wp);
    gemm_qkv<<<dim3(2, Mrows / 64, 3), 256, SMEM_GEMM>>>();
    attn_kernel<<<Mrows, 256>>>(mo);
    gemm_proj<<<dim3(2, Mrows / 64), 256, SMEM_GEMM>>>(out);
}

// round 15
// speedup vs baseline: 1.0983x; 1.0983x over previous
#include <cstdint>
#include <cuda_runtime.h>
#include <cuda_fp16.h>
#include <math.h>
#include <float.h>

// Problem constants
#define Bc    2
#define Hh    64
#define Ww    160
#define DIMc  256
#define NHc   8
#define HDc   32
#define Nn    (Hh * Ww)       // 10240 tokens per batch
#define Mrows (Bc * Nn)       // 20480 total rows
#define SCALEF 0.17677669529663687f   // 32^-0.5

// Static scratch (all activations fp16, packed half2)
__device__ uint32_t g_qh[Mrows * 128];    // q, pre-scaled by SCALEF
__device__ uint32_t g_kh[Mrows * 128];
__device__ uint32_t g_vh[Mrows * 128];
__device__ uint32_t g_xh[Mrows * 128];    // X as fp16
__device__ uint32_t g_hf[Mrows * 128];    // attn output as fp16
__device__ uint32_t g_wf[2 * 4 * 32768];  // W fp16 planes: [hi|lo][w][k][n/2]
#define WLOFF_B 524288                    // byte offset of lo planes

// ---------------------------------------------------------------------------
// helpers
// ---------------------------------------------------------------------------
__device__ __forceinline__ uint32_t smem_to_u32(const void* smem_ptr) {
    uint32_t addr;
    asm("{ .reg .u64 tmp; cvta.to.shared.u64 tmp, %1; cvt.u32.u64 %0, tmp; }"
        : "=r"(addr) : "l"(smem_ptr));
    return addr;
}

__device__ __forceinline__ uint32_t f2h2(float x, float y) {   // lo=x, hi=y
    uint32_t u;
    asm("cvt.rn.f16x2.f32 %0, %1, %2;" : "=r"(u) : "f"(y), "f"(x));
    return u;
}

__device__ __forceinline__ void mma_f16(float* c, const uint32_t* a,
                                        uint32_t b0, uint32_t b1) {
    asm volatile(
        "mma.sync.aligned.m16n8k16.row.col.f32.f16.f16.f32 "
        "{%0,%1,%2,%3},{%4,%5,%6,%7},{%8,%9},{%0,%1,%2,%3};"
        : "+f"(c[0]), "+f"(c[1]), "+f"(c[2]), "+f"(c[3])
        : "r"(a[0]), "r"(a[1]), "r"(a[2]), "r"(a[3]), "r"(b0), "r"(b1));
}

__device__ __forceinline__ void ldsm_x4(uint32_t* r, uint32_t addr) {
    asm volatile(
        "ldmatrix.sync.aligned.m8n8.x4.shared.b16 {%0,%1,%2,%3}, [%4];"
        : "=r"(r[0]), "=r"(r[1]), "=r"(r[2]), "=r"(r[3]) : "r"(addr));
}

__device__ __forceinline__ void ldsm_x4_t(uint32_t* r, uint32_t addr) {
    asm volatile(
        "ldmatrix.sync.aligned.m8n8.x4.trans.shared.b16 {%0,%1,%2,%3}, [%4];"
        : "=r"(r[0]), "=r"(r[1]), "=r"(r[2]), "=r"(r[3]) : "r"(addr));
}

#define CP16(dst, src) \
    asm volatile("cp.async.cg.shared.global [%0], [%1], 16;" :: "r"(dst), "l"(src))
#define CP_COMMIT() asm volatile("cp.async.commit_group;")
#define CP_WAIT(n)  asm volatile("cp.async.wait_group %0;" :: "n"(n))

// ---------------------------------------------------------------------------
// Conversion: X -> fp16, W -> fp16 hi/lo planes
// ---------------------------------------------------------------------------
#define XBLKS ((Mrows * 128) / 256)   // 10240

__global__ void __launch_bounds__(256)
conv_all(const float* __restrict__ x,
         const float* __restrict__ Wq, const float* __restrict__ Wk,
         const float* __restrict__ Wv, const float* __restrict__ Wp) {
    const int b = blockIdx.x;
    if (b < XBLKS) {
        size_t id = (size_t)b * 256 + threadIdx.x;
        float2 v = *reinterpret_cast<const float2*>(x + id * 2);
        g_xh[id] = f2h2(v.x, v.y);
    } else {
        int id2 = (b - XBLKS) * 256 + threadIdx.x;   // 0 .. 131071
        int w = id2 >> 15;
        int id = id2 & 32767;
        const float* src = (w == 0) ? Wq : (w == 1) ? Wk : (w == 2) ? Wv : Wp;
        float2 v = *reinterpret_cast<const float2*>(src + (size_t)id * 2);
        uint32_t h = f2h2(v.x, v.y);
        __half2 hh = *reinterpret_cast<__half2*>(&h);
        float2 hf = __half22float2(hh);
        g_wf[w * 32768 + id] = h;
        g_wf[131072 + w * 32768 + id] = f2h2(v.x - hf.x, v.y - hf.y);
    }
}

// ---------------------------------------------------------------------------
// fp16x2 GEMM: C = A_fp16 @ (Whi + Wlo).  BM=64, BN=128, 256 threads
// (8 warps, 32x32 warp tiles).  3-buffer ring of k32 chunks, cp.async,
// 3 CTAs/SM (smem 67584, regs capped via launch_bounds).
// ---------------------------------------------------------------------------
#define A_ST   5120              // 64 rows * 80 B
#define BH_ST  8704              // 32 rows * 272 B
#define SUB    22528             // A_ST + 2*BH_ST
#define SMEM_GEMM (3 * SUB)      // 67584
#define AROW_B 512               // gmem fp16 activation row bytes

__device__ __forceinline__ void issue_chunk(
    uint32_t buf, int g, const char* Ag, const char* Wh,
    uint32_t ad0, uint32_t bd0)
{
    CP16(buf + ad0, Ag + g * 64);
    const char* wh = Wh + g * 16384;         // 32 k-rows * 512 B
    CP16(buf + bd0, wh);
    CP16(buf + bd0 + 16 * 272, wh + 16 * 512);
    const char* wl = Wh + WLOFF_B + g * 16384;
    CP16(buf + bd0 + BH_ST, wl);
    CP16(buf + bd0 + BH_ST + 16 * 272, wl + 16 * 512);
    CP_COMMIT();
}

__device__ __forceinline__ void gemm_body(const uint32_t* __restrict__ Asrc,
                                          const uint32_t* __restrict__ Wplane,
                                          float* __restrict__ Cf,
                                          uint32_t* __restrict__ Ch,
                                          float qscale) {
    extern __shared__ char smem_c[];
    const uint32_t sb = smem_to_u32(smem_c);
    const int t    = threadIdx.x;
    const int warp = t >> 5;
    const int lane = t & 31;
    const int q    = lane >> 2;
    const int c4   = lane & 3;
    const int bm = blockIdx.y * 64;
    const int bn = blockIdx.x * 128;
    const int wm = (warp >> 2) * 32;
    const int wn = (warp & 3) * 32;

    const char* Ag = (const char*)Asrc + (size_t)(bm + (t >> 2)) * AROW_B + (t & 3) * 16;
    const char* Wh = (const char*)Wplane + (size_t)(t >> 4) * 512 + bn * 2 + (t & 15) * 16;
    const uint32_t ad0 = (uint32_t)((t >> 2) * 80 + (t & 3) * 16);
    const uint32_t bd0 = (uint32_t)(A_ST + (t >> 4) * 272 + (t & 15) * 16);

    float acc[2][4][4];
#pragma unroll
    for (int i = 0; i < 2; i++)
#pragma unroll
        for (int j = 0; j < 4; j++)
#pragma unroll
            for (int e = 0; e < 4; e++) acc[i][j][e] = 0.f;

    issue_chunk(sb,       0, Ag, Wh, ad0, bd0);
    issue_chunk(sb + SUB, 1, Ag, Wh, ad0, bd0);

    int cbuf = 0;
    int nbuf = 2;
#pragma unroll 1
    for (int g = 0; g < 8; g++) {
        if (g < 7) { CP_WAIT(1); } else { CP_WAIT(0); }
        __syncthreads();
        if (g < 6) {
            issue_chunk(sb + nbuf * SUB, g + 2, Ag, Wh, ad0, bd0);
            nbuf = (nbuf == 2) ? 0 : nbuf + 1;
        }

        const uint32_t abase = sb + cbuf * SUB;
        const uint32_t bhb = abase + A_ST;
        const uint32_t blb = bhb + BH_ST;
        cbuf = (cbuf == 2) ? 0 : cbuf + 1;

#pragma unroll
        for (int k16 = 0; k16 < 2; k16++) {
            uint32_t a[2][4];
#pragma unroll
            for (int mt = 0; mt < 2; mt++) {
                ldsm_x4(a[mt], abase + (wm + mt * 16 + (lane & 15)) * 80
                             + k16 * 32 + (lane >> 4) * 16);
            }
            uint32_t bh[2][4], bl[2][4];
#pragma unroll
            for (int nc = 0; nc < 2; nc++) {
                uint32_t off = (uint32_t)((k16 * 16 + (lane & 15)) * 272
                              + (wn + nc * 16 + ((lane >> 4) << 3)) * 2);
                ldsm_x4_t(bh[nc], bhb + off);
                ldsm_x4_t(bl[nc], blb + off);
            }
#pragma unroll
            for (int mt = 0; mt < 2; mt++)
#pragma unroll
                for (int n8 = 0; n8 < 4; n8++) {
                    const int nc = n8 >> 1, jj = (n8 & 1) * 2;
                    mma_f16(acc[mt][n8], a[mt], bh[nc][jj], bh[nc][jj + 1]);
                    mma_f16(acc[mt][n8], a[mt], bl[nc][jj], bl[nc][jj + 1]);
                }
        }
    }

    // epilogue
    if (Ch) {
#pragma unroll
        for (int mt = 0; mt < 2; mt++)
#pragma unroll
            for (int n8 = 0; n8 < 4; n8++) {
                const int gr0 = bm + wm + mt * 16 + q;
                const int gc  = bn + wn + n8 * 8 + 2 * c4;
                Ch[(size_t)gr0 * 128 + (gc >> 1)] =
                    f2h2(acc[mt][n8][0] * qscale, acc[mt][n8][1] * qscale);
                Ch[(size_t)(gr0 + 8) * 128 + (gc >> 1)] =
                    f2h2(acc[mt][n8][2] * qscale, acc[mt][n8][3] * qscale);
            }
    } else {
#pragma unroll
        for (int mt = 0; mt < 2; mt++)
#pragma unroll
            for (int n8 = 0; n8 < 4; n8++) {
                const int gr0 = bm + wm + mt * 16 + q;
                const int gc  = bn + wn + n8 * 8 + 2 * c4;
                *reinterpret_cast<float2*>(Cf + (size_t)gr0 * DIMc + gc) =
                    make_float2(acc[mt][n8][0], acc[mt][n8][1]);
                *reinterpret_cast<float2*>(Cf + (size_t)(gr0 + 8) * DIMc + gc) =
                    make_float2(acc[mt][n8][2], acc[mt][n8][3]);
            }
    }
}

__global__ void __launch_bounds__(256, 3)
gemm_qkv() {
    const int z = blockIdx.z;
    uint32_t* Ch = (z == 0) ? g_qh : (z == 1) ? g_kh : g_vh;
    gemm_body(g_xh, g_wf + z * 32768, nullptr, Ch, (z == 0) ? SCALEF : 1.f);
}

__global__ void __launch_bounds__(256, 3)
gemm_proj(float* __restrict__ out) {
    gemm_body(g_hf, g_wf + 3 * 32768, out, nullptr, 1.f);
}

// ---------------------------------------------------------------------------
// Attention (R13-proven): fp16 Q/K/V direct gather, 4 dims per lane,
// 4 position-groups per warp.
// ---------------------------------------------------------------------------
__global__ void __launch_bounds__(256, 6)
attn_kernel(const float* __restrict__ mo) {
    const int r = blockIdx.x;
    const int bofs = (r >= Nn) ? Nn : 0;
    const int hd = threadIdx.x >> 5;
    const int lane = threadIdx.x & 31;
    const int g  = lane & 7;              // dim group (4 dims)
    const int sd = lane >> 3;             // window column 0..3

    float2 o2 = *reinterpret_cast<const float2*>(mo + (size_t)r * 2);
    float ox = fminf(fmaxf(o2.x, 1.0f), (float)(Ww - 2) - 0.001f);
    float oy = fminf(fmaxf(o2.y, 1.0f), (float)(Hh - 2) - 0.001f);
    const float mx = floorf(ox), my = floorf(oy);
    const float fx = ox - mx,   fy = oy - my;

    const int ibase = bofs + ((int)my - 1) * Ww + ((int)mx - 1);

    uint2 qq = *reinterpret_cast<const uint2*>(
        g_qh + (size_t)r * 128 + hd * 16 + g * 2);
    const float2 q01 = __half22float2(*reinterpret_cast<const __half2*>(&qq.x));
    const float2 q23 = __half22float2(*reinterpret_cast<const __half2*>(&qq.y));

    const uint32_t* kp = g_kh + (size_t)ibase * 128 + hd * 16 + g * 2;
    const uint32_t* vp = g_vh + (size_t)ibase * 128 + hd * 16 + g * 2;

    int roff[4];
    float part[4];
#pragma unroll
    for (int i = 0; i < 4; i++) {
        roff[i] = (i * Ww + sd) * 128;
        uint2 kk = *reinterpret_cast<const uint2*>(kp + roff[i]);
        float2 k01 = __half22float2(*reinterpret_cast<const __half2*>(&kk.x));
        float2 k23 = __half22float2(*reinterpret_cast<const __half2*>(&kk.y));
        part[i] = q01.x * k01.x + q01.y * k01.y + q23.x * k23.x + q23.y * k23.y;
    }

    float u2[2];
    {
        const bool hb = (lane & 4) != 0;
#pragma unroll
        for (int j = 0; j < 2; j++) {
            float keep = hb ? part[j + 2] : part[j];
            float send = hb ? part[j] : part[j + 2];
            u2[j] = keep + __shfl_xor_sync(0xffffffffu, send, 4);
        }
    }
    float u1;
    {
        const bool hb = (lane & 2) != 0;
        float keep = hb ? u2[1] : u2[0];
        float send = hb ? u2[0] : u2[1];
        u1 = keep + __shfl_xor_sync(0xffffffffu, send, 2);
    }
    const float s = u1 + __shfl_xor_sync(0xffffffffu, u1, 1);

    const int i_mine = (lane >> 1) & 3;
    const float wxv = (sd == 0) ? (1.f - fx) : ((sd == 3) ? fx : 1.f);
    const float wyv = (i_mine == 0) ? (1.f - fy) : ((i_mine == 3) ? fy : 1.f);
    const float bw = wxv * wyv;

    float mval = s;
#pragma unroll
    for (int o = 16; o > 0; o >>= 1)
        mval = fmaxf(mval, __shfl_xor_sync(0xffffffffu, mval, o));
    const float e = __expf(s - mval) * bw;
    float se = e;
#pragma unroll
    for (int o = 16; o > 0; o >>= 1)
        se += __shfl_xor_sync(0xffffffffu, se, o);
    const float p = __fdividef(e, 0.5f * se);

    float f0 = 0.f, f1 = 0.f, f2 = 0.f, f3 = 0.f;
#pragma unroll
    for (int i = 0; i < 4; i++) {
        uint2 vv = *reinterpret_cast<const uint2*>(vp + roff[i]);
        float2 v01 = __half22float2(*reinterpret_cast<const __half2*>(&vv.x));
        float2 v23 = __half22float2(*reinterpret_cast<const __half2*>(&vv.y));
        float pa = __shfl_sync(0xffffffffu, p, (lane & 24) | (i << 1));
        f0 += pa * v01.x;
        f1 += pa * v01.y;
        f2 += pa * v23.x;
        f3 += pa * v23.y;
    }
#pragma unroll
    for (int o = 8; o <= 16; o <<= 1) {
        f0 += __shfl_xor_sync(0xffffffffu, f0, o);
        f1 += __shfl_xor_sync(0xffffffffu, f1, o);
        f2 += __shfl_xor_sync(0xffffffffu, f2, o);
        f3 += __shfl_xor_sync(0xffffffffu, f3, o);
    }

    if (sd == 0) {
        uint2 o;
        o.x = f2h2(f0, f1);
        o.y = f2h2(f2, f3);
        *reinterpret_cast<uint2*>(g_hf + (size_t)r * 128 + hd * 16 + g * 2) = o;
    }
}

// ---------------------------------------------------------------------------
extern "C" void kernel_launch(void* const* d_in, const int* in_sizes, int n_in,
                              void* d_out, int out_size) {
    const float* x  = (const float*)d_in[0];
    const float* mo = (const float*)d_in[1];
    const float* Wq = (const float*)d_in[2];
    const float* Wk = (const float*)d_in[3];
    const float* Wv = (const float*)d_in[4];
    const float* Wp = (const float*)d_in[5];
    float* out = (float*)d_out;

    cudaFuncSetAttribute(gemm_qkv, cudaFuncAttributeMaxDynamicSharedMemorySize, SMEM_GEMM);
    cudaFuncSetAttribute(gemm_proj, cudaFuncAttributeMaxDynamicSharedMemorySize, SMEM_GEMM);

    conv_all<<<XBLKS + 512, 256>>>(x, Wq, Wk, Wv, Wp);
    gemm_qkv<<<dim3(2, Mrows / 64, 3), 256, SMEM_GEMM>>>();
    attn_kernel<<<Mrows, 256>>>(mo);
    gemm_proj<<<dim3(2, Mrows / 64), 256, SMEM_GEMM>>>(out);
}

// round 16
// speedup vs baseline: 1.2399x; 1.1289x over previous
#include <cstdint>
#include <cuda_runtime.h>
#include <cuda_fp16.h>
#include <math.h>
#include <float.h>

// Problem constants
#define Bc    2
#define Hh    64
#define Ww    160
#define DIMc  256
#define NHc   8
#define HDc   32
#define Nn    (Hh * Ww)       // 10240 tokens per batch
#define Mrows (Bc * Nn)       // 20480 total rows
#define SCALEF 0.17677669529663687f   // 32^-0.5

// Static scratch (all activations fp16, packed half2)
__device__ uint32_t g_qh[Mrows * 128];    // q, pre-scaled by SCALEF
__device__ uint32_t g_kh[Mrows * 128];
__device__ uint32_t g_vh[Mrows * 128];
__device__ uint32_t g_xh[Mrows * 128];    // X as fp16
__device__ uint32_t g_hf[Mrows * 128];    // attn output as fp16
__device__ uint32_t g_wf[2 * 4 * 32768];  // W fp16 planes: [hi|lo][w][k][n/2]
#define WLOFF_B 524288                    // byte offset of lo planes

// ---------------------------------------------------------------------------
// helpers
// ---------------------------------------------------------------------------
__device__ __forceinline__ uint32_t smem_to_u32(const void* smem_ptr) {
    uint32_t addr;
    asm("{ .reg .u64 tmp; cvta.to.shared.u64 tmp, %1; cvt.u32.u64 %0, tmp; }"
        : "=r"(addr) : "l"(smem_ptr));
    return addr;
}

__device__ __forceinline__ uint32_t f2h2(float x, float y) {   // lo=x, hi=y
    uint32_t u;
    asm("cvt.rn.f16x2.f32 %0, %1, %2;" : "=r"(u) : "f"(y), "f"(x));
    return u;
}

__device__ __forceinline__ void mma_f16(float* c, const uint32_t* a,
                                        uint32_t b0, uint32_t b1) {
    asm volatile(
        "mma.sync.aligned.m16n8k16.row.col.f32.f16.f16.f32 "
        "{%0,%1,%2,%3},{%4,%5,%6,%7},{%8,%9},{%0,%1,%2,%3};"
        : "+f"(c[0]), "+f"(c[1]), "+f"(c[2]), "+f"(c[3])
        : "r"(a[0]), "r"(a[1]), "r"(a[2]), "r"(a[3]), "r"(b0), "r"(b1));
}

__device__ __forceinline__ void ldsm_x4(uint32_t* r, uint32_t addr) {
    asm volatile(
        "ldmatrix.sync.aligned.m8n8.x4.shared.b16 {%0,%1,%2,%3}, [%4];"
        : "=r"(r[0]), "=r"(r[1]), "=r"(r[2]), "=r"(r[3]) : "r"(addr));
}

__device__ __forceinline__ void ldsm_x4_t(uint32_t* r, uint32_t addr) {
    asm volatile(
        "ldmatrix.sync.aligned.m8n8.x4.trans.shared.b16 {%0,%1,%2,%3}, [%4];"
        : "=r"(r[0]), "=r"(r[1]), "=r"(r[2]), "=r"(r[3]) : "r"(addr));
}

#define CP16(dst, src) \
    asm volatile("cp.async.cg.shared.global [%0], [%1], 16;" :: "r"(dst), "l"(src))
#define CP_COMMIT() asm volatile("cp.async.commit_group;")
#define CP_WAIT(n)  asm volatile("cp.async.wait_group %0;" :: "n"(n))

// ---------------------------------------------------------------------------
// Conversion: X -> fp16, W -> fp16 hi/lo planes
// ---------------------------------------------------------------------------
#define XBLKS ((Mrows * 128) / 256)   // 10240

__global__ void __launch_bounds__(256)
conv_all(const float* __restrict__ x,
         const float* __restrict__ Wq, const float* __restrict__ Wk,
         const float* __restrict__ Wv, const float* __restrict__ Wp) {
    const int b = blockIdx.x;
    if (b < XBLKS) {
        size_t id = (size_t)b * 256 + threadIdx.x;
        float2 v = *reinterpret_cast<const float2*>(x + id * 2);
        g_xh[id] = f2h2(v.x, v.y);
    } else {
        int id2 = (b - XBLKS) * 256 + threadIdx.x;   // 0 .. 131071
        int w = id2 >> 15;
        int id = id2 & 32767;
        const float* src = (w == 0) ? Wq : (w == 1) ? Wk : (w == 2) ? Wv : Wp;
        float2 v = *reinterpret_cast<const float2*>(src + (size_t)id * 2);
        uint32_t h = f2h2(v.x, v.y);
        __half2 hh = *reinterpret_cast<__half2*>(&h);
        float2 hf = __half22float2(hh);
        g_wf[w * 32768 + id] = h;
        g_wf[131072 + w * 32768 + id] = f2h2(v.x - hf.x, v.y - hf.y);
    }
}

// ---------------------------------------------------------------------------
// fp16x2 GEMM (R15-proven): C = A_fp16 @ (Whi + Wlo).  BM=64, BN=128,
// 256 threads, 3-buffer ring of k32 chunks, cp.async, 3 CTAs/SM.
// ---------------------------------------------------------------------------
#define A_ST   5120              // 64 rows * 80 B
#define BH_ST  8704              // 32 rows * 272 B
#define SUB    22528             // A_ST + 2*BH_ST
#define SMEM_GEMM (3 * SUB)      // 67584
#define AROW_B 512               // gmem fp16 activation row bytes

__device__ __forceinline__ void issue_chunk(
    uint32_t buf, int g, const char* Ag, const char* Wh,
    uint32_t ad0, uint32_t bd0)
{
    CP16(buf + ad0, Ag + g * 64);
    const char* wh = Wh + g * 16384;         // 32 k-rows * 512 B
    CP16(buf + bd0, wh);
    CP16(buf + bd0 + 16 * 272, wh + 16 * 512);
    const char* wl = Wh + WLOFF_B + g * 16384;
    CP16(buf + bd0 + BH_ST, wl);
    CP16(buf + bd0 + BH_ST + 16 * 272, wl + 16 * 512);
    CP_COMMIT();
}

__device__ __forceinline__ void gemm_body(const uint32_t* __restrict__ Asrc,
                                          const uint32_t* __restrict__ Wplane,
                                          float* __restrict__ Cf,
                                          uint32_t* __restrict__ Ch,
                                          float qscale) {
    extern __shared__ char smem_c[];
    const uint32_t sb = smem_to_u32(smem_c);
    const int t    = threadIdx.x;
    const int warp = t >> 5;
    const int lane = t & 31;
    const int q    = lane >> 2;
    const int c4   = lane & 3;
    const int bm = blockIdx.y * 64;
    const int bn = blockIdx.x * 128;
    const int wm = (warp >> 2) * 32;
    const int wn = (warp & 3) * 32;

    const char* Ag = (const char*)Asrc + (size_t)(bm + (t >> 2)) * AROW_B + (t & 3) * 16;
    const char* Wh = (const char*)Wplane + (size_t)(t >> 4) * 512 + bn * 2 + (t & 15) * 16;
    const uint32_t ad0 = (uint32_t)((t >> 2) * 80 + (t & 3) * 16);
    const uint32_t bd0 = (uint32_t)(A_ST + (t >> 4) * 272 + (t & 15) * 16);

    float acc[2][4][4];
#pragma unroll
    for (int i = 0; i < 2; i++)
#pragma unroll
        for (int j = 0; j < 4; j++)
#pragma unroll
            for (int e = 0; e < 4; e++) acc[i][j][e] = 0.f;

    issue_chunk(sb,       0, Ag, Wh, ad0, bd0);
    issue_chunk(sb + SUB, 1, Ag, Wh, ad0, bd0);

    int cbuf = 0;
    int nbuf = 2;
#pragma unroll 1
    for (int g = 0; g < 8; g++) {
        if (g < 7) { CP_WAIT(1); } else { CP_WAIT(0); }
        __syncthreads();
        if (g < 6) {
            issue_chunk(sb + nbuf * SUB, g + 2, Ag, Wh, ad0, bd0);
            nbuf = (nbuf == 2) ? 0 : nbuf + 1;
        }

        const uint32_t abase = sb + cbuf * SUB;
        const uint32_t bhb = abase + A_ST;
        const uint32_t blb = bhb + BH_ST;
        cbuf = (cbuf == 2) ? 0 : cbuf + 1;

#pragma unroll
        for (int k16 = 0; k16 < 2; k16++) {
            uint32_t a[2][4];
#pragma unroll
            for (int mt = 0; mt < 2; mt++) {
                ldsm_x4(a[mt], abase + (wm + mt * 16 + (lane & 15)) * 80
                             + k16 * 32 + (lane >> 4) * 16);
            }
            uint32_t bh[2][4], bl[2][4];
#pragma unroll
            for (int nc = 0; nc < 2; nc++) {
                uint32_t off = (uint32_t)((k16 * 16 + (lane & 15)) * 272
                              + (wn + nc * 16 + ((lane >> 4) << 3)) * 2);
                ldsm_x4_t(bh[nc], bhb + off);
                ldsm_x4_t(bl[nc], blb + off);
            }
#pragma unroll
            for (int mt = 0; mt < 2; mt++)
#pragma unroll
                for (int n8 = 0; n8 < 4; n8++) {
                    const int nc = n8 >> 1, jj = (n8 & 1) * 2;
                    mma_f16(acc[mt][n8], a[mt], bh[nc][jj], bh[nc][jj + 1]);
                    mma_f16(acc[mt][n8], a[mt], bl[nc][jj], bl[nc][jj + 1]);
                }
        }
    }

    // epilogue
    if (Ch) {
#pragma unroll
        for (int mt = 0; mt < 2; mt++)
#pragma unroll
            for (int n8 = 0; n8 < 4; n8++) {
                const int gr0 = bm + wm + mt * 16 + q;
                const int gc  = bn + wn + n8 * 8 + 2 * c4;
                Ch[(size_t)gr0 * 128 + (gc >> 1)] =
                    f2h2(acc[mt][n8][0] * qscale, acc[mt][n8][1] * qscale);
                Ch[(size_t)(gr0 + 8) * 128 + (gc >> 1)] =
                    f2h2(acc[mt][n8][2] * qscale, acc[mt][n8][3] * qscale);
            }
    } else {
#pragma unroll
        for (int mt = 0; mt < 2; mt++)
#pragma unroll
            for (int n8 = 0; n8 < 4; n8++) {
                const int gr0 = bm + wm + mt * 16 + q;
                const int gc  = bn + wn + n8 * 8 + 2 * c4;
                *reinterpret_cast<float2*>(Cf + (size_t)gr0 * DIMc + gc) =
                    make_float2(acc[mt][n8][0], acc[mt][n8][1]);
                *reinterpret_cast<float2*>(Cf + (size_t)(gr0 + 8) * DIMc + gc) =
                    make_float2(acc[mt][n8][2], acc[mt][n8][3]);
            }
    }
}

__global__ void __launch_bounds__(256, 3)
gemm_qkv() {
    const int z = blockIdx.z;
    uint32_t* Ch = (z == 0) ? g_qh : (z == 1) ? g_kh : g_vh;
    gemm_body(g_xh, g_wf + z * 32768, nullptr, Ch, (z == 0) ? SCALEF : 1.f);
}

__global__ void __launch_bounds__(256, 3)
gemm_proj(float* __restrict__ out) {
    gemm_body(g_hf, g_wf + 3 * 32768, out, nullptr, 1.f);
}

// ---------------------------------------------------------------------------
// Attention v4: head-pair warps, full 128 B gather wavefronts.
// Block = 256 threads = 2 tokens x 4 warps. Warp: token = w>>2, hp = w&3
// (heads 2hp, 2hp+1 = 64 dims = 128 B per window row).
// Lane: u = lane&15 (uint2 slice of the 128 B), sd = lane>>4 (position parity).
// Load i (0..7) covers position a = 2i + sd.  After 8-value butterfly
// (offsets 4,2,1), lane holds score of a = 2*(lane&7)+sd for head (lane>>3)&1.
// ---------------------------------------------------------------------------
__global__ void __launch_bounds__(256, 6)
attn_kernel(const float* __restrict__ mo) {
    const int w = threadIdx.x >> 5;
    const int r = blockIdx.x * 2 + (w >> 2);
    const int hp = w & 3;                 // head pair
    const int bofs = (r >= Nn) ? Nn : 0;
    const int lane = threadIdx.x & 31;
    const int u  = lane & 15;             // uint2 index in 128 B row slice
    const int sd = lane >> 4;             // position parity

    float2 o2 = *reinterpret_cast<const float2*>(mo + (size_t)r * 2);
    float ox = fminf(fmaxf(o2.x, 1.0f), (float)(Ww - 2) - 0.001f);
    float oy = fminf(fmaxf(o2.y, 1.0f), (float)(Hh - 2) - 0.001f);
    const float mx = floorf(ox), my = floorf(oy);
    const float fx = ox - mx,   fy = oy - my;
    const int ibase = bofs + ((int)my - 1) * Ww + ((int)mx - 1);

    const int woff = hp * 32 + u * 2;     // word offset within a row
    uint2 qq = *reinterpret_cast<const uint2*>(g_qh + (size_t)r * 128 + woff);
    const float2 q01 = __half22float2(*reinterpret_cast<const __half2*>(&qq.x));
    const float2 q23 = __half22float2(*reinterpret_cast<const __half2*>(&qq.y));

    const uint32_t* kp = g_kh + (size_t)ibase * 128 + woff;
    const uint32_t* vp = g_vh + (size_t)ibase * 128 + woff;

    int roff[8];
    float part[8];
#pragma unroll
    for (int i = 0; i < 8; i++) {
        int a = 2 * i + sd;
        roff[i] = ((a >> 2) * Ww + (a & 3)) * 128;
        uint2 kk = *reinterpret_cast<const uint2*>(kp + roff[i]);
        float2 k01 = __half22float2(*reinterpret_cast<const __half2*>(&kk.x));
        float2 k23 = __half22float2(*reinterpret_cast<const __half2*>(&kk.y));
        part[i] = q01.x * k01.x + q01.y * k01.y + q23.x * k23.x + q23.y * k23.y;
    }

    // 8-value butterfly within 8-lane groups (offsets 4,2,1).
    // After: lane holds full score of i_mine = lane&7.
    float v4[4];
    {
        const bool hb = (lane & 4) != 0;
#pragma unroll
        for (int j = 0; j < 4; j++) {
            float keep = hb ? part[j + 4] : part[j];
            float send = hb ? part[j] : part[j + 4];
            v4[j] = keep + __shfl_xor_sync(0xffffffffu, send, 4);
        }
    }
    float v2[2];
    {
        const bool hb = (lane & 2) != 0;
#pragma unroll
        for (int j = 0; j < 2; j++) {
            float keep = hb ? v4[j + 2] : v4[j];
            float send = hb ? v4[j] : v4[j + 2];
            v2[j] = keep + __shfl_xor_sync(0xffffffffu, send, 2);
        }
    }
    float s;
    {
        const bool hb = (lane & 1) != 0;
        float keep = hb ? v2[1] : v2[0];
        float send = hb ? v2[0] : v2[1];
        s = keep + __shfl_xor_sync(0xffffffffu, send, 1);
    }
    // score of a_mine = 2*(lane&7) + sd, head bit = (lane>>3)&1

    const int a_mine = 2 * (lane & 7) + sd;
    const int axp = a_mine & 3;
    const int ayp = a_mine >> 2;
    const float wxv = (axp == 0) ? (1.f - fx) : ((axp == 3) ? fx : 1.f);
    const float wyv = (ayp == 0) ? (1.f - fy) : ((ayp == 3) ? fy : 1.f);
    const float bw = wxv * wyv;

    // softmax over the 16 lanes sharing the head bit (xor 16,4,2,1)
    float mval = s;
    mval = fmaxf(mval, __shfl_xor_sync(0xffffffffu, mval, 16));
    mval = fmaxf(mval, __shfl_xor_sync(0xffffffffu, mval, 4));
    mval = fmaxf(mval, __shfl_xor_sync(0xffffffffu, mval, 2));
    mval = fmaxf(mval, __shfl_xor_sync(0xffffffffu, mval, 1));
    const float e = __expf(s - mval) * bw;
    float se = e;
    se += __shfl_xor_sync(0xffffffffu, se, 16);
    se += __shfl_xor_sync(0xffffffffu, se, 4);
    se += __shfl_xor_sync(0xffffffffu, se, 2);
    se += __shfl_xor_sync(0xffffffffu, se, 1);
    const float p = __fdividef(e, se);

    // V accumulate: p for a = 2i+sd (own sd, own head) lives in lane (lane&24)|i
    float f0 = 0.f, f1 = 0.f, f2 = 0.f, f3 = 0.f;
#pragma unroll
    for (int i = 0; i < 8; i++) {
        uint2 vv = *reinterpret_cast<const uint2*>(vp + roff[i]);
        float2 v01 = __half22float2(*reinterpret_cast<const __half2*>(&vv.x));
        float2 v23 = __half22float2(*reinterpret_cast<const __half2*>(&vv.y));
        float pa = __shfl_sync(0xffffffffu, p, (lane & 24) | i);
        f0 += pa * v01.x;
        f1 += pa * v01.y;
        f2 += pa * v23.x;
        f3 += pa * v23.y;
    }
    // combine even/odd position parities (lanes sd=0 <-> sd=1, same u)
    f0 += __shfl_xor_sync(0xffffffffu, f0, 16);
    f1 += __shfl_xor_sync(0xffffffffu, f1, 16);
    f2 += __shfl_xor_sync(0xffffffffu, f2, 16);
    f3 += __shfl_xor_sync(0xffffffffu, f3, 16);

    if (sd == 0) {
        uint2 o;
        o.x = f2h2(f0, f1);
        o.y = f2h2(f2, f3);
        *reinterpret_cast<uint2*>(g_hf + (size_t)r * 128 + woff) = o;
    }
}

// ---------------------------------------------------------------------------
extern "C" void kernel_launch(void* const* d_in, const int* in_sizes, int n_in,
                              void* d_out, int out_size) {
    const float* x  = (const float*)d_in[0];
    const float* mo = (const float*)d_in[1];
    const float* Wq = (const float*)d_in[2];
    const float* Wk = (const float*)d_in[3];
    const float* Wv = (const float*)d_in[4];
    const float* Wp = (const float*)d_in[5];
    float* out = (float*)d_out;

    cudaFuncSetAttribute(gemm_qkv, cudaFuncAttributeMaxDynamicSharedMemorySize, SMEM_GEMM);
    cudaFuncSetAttribute(gemm_proj, cudaFuncAttributeMaxDynamicSharedMemorySize, SMEM_GEMM);

    conv_all<<<XBLKS + 512, 256>>>(x, Wq, Wk, Wv, Wp);
    gemm_qkv<<<dim3(2, Mrows / 64, 3), 256, SMEM_GEMM>>>();
    attn_kernel<<<Mrows / 2, 256>>>(mo);
    gemm_proj<<<dim3(2, Mrows / 64), 256, SMEM_GEMM>>>(out);
}